// round 15
// baseline (speedup 1.0000x reference)
#include <cuda_runtime.h>

#define EMB   64
#define NSPH  16
#define KMAX  24
#define MAX_EDGES 131072
#define NBLOCKS 456              // 3 CTAs/SM * 152
#define NW      (NBLOCKS * 4)    // persistent warps

// dynamic smem layout (floats, per CTA):
//   rbf:  wrp*1024                      (4KB/warp, single buffer)
//   sph:  4096 + wrp*384                (1.5KB/warp, single buffer)
//   m:    5632 + (wrp*2 + b)*1536       (6KB/warp x2, double buffer)
#define SMEM_FLOATS (5632 + 8 * 1536)    // 17920 floats = 71680 B

__device__ int    g_start[MAX_EDGES];
__device__ int    g_count[MAX_EDGES];
// W in mma-fragment order, 2 kt-frags packed per float4:
// g_Wf4[(j*8+nt)*32 + lane] = {b0(kt=2j), b1(kt=2j), b0(kt=2j+1), b1(kt=2j+1)}
__device__ float4 g_Wf4[32 * 32];

__global__ void prep_kernel(const int* __restrict__ id_reduce,
                            const int* __restrict__ Kidx,
                            const float* __restrict__ w, int nT)
{
    int t = blockIdx.x * blockDim.x + threadIdx.x;
    if (t < 1024) {
        int entry = t >> 5, lane = t & 31;
        int j  = entry >> 3, nt = entry & 7;
        int gid = lane >> 2, tig = lane & 3;
        int d = nt * 8 + gid;
        float v[4];
        #pragma unroll
        for (int h = 0; h < 2; h++) {
            int i = (2 * j + h) * 8 + tig;
            unsigned r0, r1;
            asm("cvt.rna.tf32.f32 %0, %1;" : "=r"(r0) : "f"(w[d * EMB + i]));
            asm("cvt.rna.tf32.f32 %0, %1;" : "=r"(r1) : "f"(w[d * EMB + i + 4]));
            v[2 * h]     = __uint_as_float(r0);
            v[2 * h + 1] = __uint_as_float(r1);
        }
        g_Wf4[t] = make_float4(v[0], v[1], v[2], v[3]);
    }
    if (t < nT) {
        int e = id_reduce[t];
        if (t == 0 || id_reduce[t - 1] != e) g_start[e] = t;
        if (t == nT - 1 || id_reduce[t + 1] != e) g_count[e] = Kidx[t] + 1;
    }
}

__device__ __forceinline__ unsigned tf32r(float x) {
    unsigned u; asm("cvt.rna.tf32.f32 %0, %1;" : "=r"(u) : "f"(x)); return u;
}

__device__ __forceinline__ void mma_tf32(float c[4], const unsigned a[4],
                                         unsigned b0, unsigned b1)
{
    asm volatile(
        "mma.sync.aligned.m16n8k8.row.col.f32.tf32.tf32.f32 "
        "{%0,%1,%2,%3},{%4,%5,%6,%7},{%8,%9},{%0,%1,%2,%3};"
        : "+f"(c[0]), "+f"(c[1]), "+f"(c[2]), "+f"(c[3])
        : "r"(a[0]), "r"(a[1]), "r"(a[2]), "r"(a[3]), "r"(b0), "r"(b1));
}

// Issue one edge's full cp.async group (rbf + m + sph, XOR-swizzled) and commit.
__device__ __forceinline__ void issue_edge(const float* __restrict__ rbf,
                                           const float* __restrict__ sph,
                                           const float* __restrict__ m,
                                           int e, int st, int ct,
                                           unsigned rsb, unsigned ssb, unsigned msb,
                                           int lane)
{
    // rbf[i][s] at i*16 + (s ^ ((i&2)<<2))  [chunk ^ (row&2)]
    const float* rg = rbf + (size_t)e * (EMB * NSPH);
    #pragma unroll
    for (int it = 0; it < 8; it++) {
        int chunk = it * 32 + lane;
        int row = chunk >> 2, c = chunk & 3;
        int dc = c ^ (row & 2);
        unsigned dst = rsb + (unsigned)(row * NSPH + dc * 4) * 4u;
        asm volatile("cp.async.cg.shared.global [%0], [%1], 16;"
                     :: "r"(dst), "l"(rg + chunk * 4));
    }
    // m[t][d] at t*64 + (d ^ ((t&3)*8)), rows >= ct zfilled
    const float* mg = m + (size_t)st * EMB;
    #pragma unroll
    for (int it = 0; it < 12; it++) {
        int chunk = it * 32 + lane;
        int row = chunk >> 4, c = chunk & 15;
        int dc = c ^ ((row & 3) << 1);
        unsigned dst = msb + (unsigned)(row * EMB + dc * 4) * 4u;
        int srow = (row < ct) ? row : 0;
        int sz   = (row < ct) ? 16 : 0;
        asm volatile("cp.async.cg.shared.global [%0], [%1], 16, %2;"
                     :: "r"(dst), "l"(mg + srow * EMB + c * 4), "r"(sz));
    }
    // sph[s][k] at s*24 + (k ^ (s&4))
    const float* sg = sph + (size_t)e * (NSPH * KMAX);
    #pragma unroll
    for (int it = 0; it < 3; it++) {
        int chunk = it * 32 + lane;
        int row = chunk / 6, c = chunk % 6;
        int dc = c ^ ((row & 4) >> 2);
        unsigned dst = ssb + (unsigned)(row * KMAX + dc * 4) * 4u;
        asm volatile("cp.async.cg.shared.global [%0], [%1], 16;"
                     :: "r"(dst), "l"(sg + row * KMAX + c * 4));
    }
    asm volatile("cp.async.commit_group;");
}

// Persistent warps, distance-1 pipeline: wait(group e) -> extract ra/sa ->
// issue group(e+NW) [rbf/sph single-buffered, m double] -> P phase (W
// L1-resident) -> Q phase from m buffer b -> Hadamard/reduce/store.
__global__ void __launch_bounds__(128, 3)
main_kernel(const float* __restrict__ rbf,
            const float* __restrict__ sph,
            const float* __restrict__ m,
            float* __restrict__ out, int nEdges)
{
    extern __shared__ float smem[];

    const int lane = threadIdx.x & 31;
    const int wrp  = threadIdx.x >> 5;
    const int gid  = lane >> 2;   // 0..7
    const int tig  = lane & 3;    // 0..3

    const float* rp  = smem + wrp * 1024;
    const float* sp  = smem + 4096 + wrp * 384;
    const float* mp0 = smem + 5632 + wrp * 2 * 1536;

    const unsigned sbase = (unsigned)__cvta_generic_to_shared(smem);
    const unsigned rsb  = sbase + (unsigned)(wrp * 1024) * 4u;
    const unsigned ssb  = sbase + (unsigned)(4096 + wrp * 384) * 4u;
    const unsigned msb0 = sbase + (unsigned)(5632 + wrp * 2 * 1536) * 4u;

    const int e0 = blockIdx.x * 4 + wrp;
    if (e0 >= nEdges) return;

    // ---- prologue: stage edge e0 into parity 0; prefetch e0+NW's run info ----
    {
        int st = __ldg(&g_start[e0]);
        int ct = __ldg(&g_count[e0]);
        issue_edge(rbf, sph, m, e0, st, ct, rsb, ssb, msb0, lane);
    }
    int epn = e0 + NW; if (epn >= nEdges) epn = 0;
    int stN = __ldg(&g_start[epn]);
    int ctN = __ldg(&g_count[epn]);

    int b = 0;
    for (int e = e0; e < nEdges; e += NW) {
        asm volatile("cp.async.wait_group 0;");
        __syncwarp();

        // ---- extract ra (rbf) and sa (sph) from swizzled smem ----
        unsigned ra[8][4];
        {
            const int f = (tig & 2) << 2;             // s-xor-8 when i&2
            #pragma unroll
            for (int kt = 0; kt < 8; kt++) {
                int i = kt * 8 + tig;
                ra[kt][0] = tf32r(rp[i * NSPH + (gid ^ f)]);
                ra[kt][1] = tf32r(rp[i * NSPH + ((gid + 8) ^ f)]);
                ra[kt][2] = tf32r(rp[(i + 4) * NSPH + (gid ^ f)]);
                ra[kt][3] = tf32r(rp[(i + 4) * NSPH + ((gid + 8) ^ f)]);
            }
        }
        unsigned sa[3][4];
        {
            const int h = gid & 4;
            #pragma unroll
            for (int kt = 0; kt < 3; kt++) {
                int t = kt * 8 + tig;
                sa[kt][0] = tf32r(sp[gid * KMAX + (t ^ h)]);
                sa[kt][1] = tf32r(sp[(gid + 8) * KMAX + (t ^ h)]);
                sa[kt][2] = tf32r(sp[gid * KMAX + ((t + 4) ^ h)]);
                sa[kt][3] = tf32r(sp[(gid + 8) * KMAX + ((t + 4) ^ h)]);
            }
        }

        // ---- issue next edge's group into m parity b^1 (rbf/sph reuse OK:
        //      their data arrives ~600cyc after the 29cyc LDS reads above) ----
        {
            int ep1 = e + NW; if (ep1 >= nEdges) ep1 = 0;
            issue_edge(rbf, sph, m, ep1, stN, ctN,
                       rsb, ssb, msb0 + (unsigned)((b ^ 1) * 1536) * 4u, lane);
            int ep2 = e + 2 * NW; if (ep2 >= nEdges) ep2 = 0;
            stN = __ldg(&g_start[ep2]);
            ctN = __ldg(&g_count[ep2]);
        }

        // ---- P phase: p[nt] = rbf^T x Wt (W L1-resident float4) ----
        float p[8][4];
        #pragma unroll
        for (int nt = 0; nt < 8; nt++) {
            p[nt][0] = p[nt][1] = p[nt][2] = p[nt][3] = 0.f;
            #pragma unroll
            for (int j = 0; j < 4; j++) {
                float4 wf = __ldg(&g_Wf4[(j * 8 + nt) * 32 + lane]);
                mma_tf32(p[nt], ra[2 * j],     __float_as_uint(wf.x), __float_as_uint(wf.y));
                mma_tf32(p[nt], ra[2 * j + 1], __float_as_uint(wf.z), __float_as_uint(wf.w));
            }
        }

        // ---- Q phase from m buffer b; Hadamard; s-reduction; store ----
        const float* mpb = mp0 + b * 1536;
        const int gsw = tig * 8;                      // m swizzle: d ^ ((t&3)*8)
        #pragma unroll
        for (int nt = 0; nt < 8; nt++) {
            float q[4] = {0.f, 0.f, 0.f, 0.f};
            #pragma unroll
            for (int kt = 0; kt < 3; kt++) {
                int t = kt * 8 + tig;
                int col = (nt * 8 + gid) ^ gsw;
                unsigned b0 = tf32r(mpb[t * EMB + col]);
                unsigned b1 = tf32r(mpb[(t + 4) * EMB + col]);
                mma_tf32(q, sa[kt], b0, b1);
            }

            // c0:(s=gid, d=2tig) c1:(gid, 2tig+1) c2:(gid+8, 2tig) c3:(gid+8, 2tig+1)
            float h00 = p[nt][0] * q[0] + p[nt][2] * q[2];
            float h01 = p[nt][1] * q[1] + p[nt][3] * q[3];
            #pragma unroll
            for (int off = 4; off <= 16; off <<= 1) {
                h00 += __shfl_xor_sync(0xffffffffu, h00, off);
                h01 += __shfl_xor_sync(0xffffffffu, h01, off);
            }
            if (gid == 0)
                *(float2*)(out + (size_t)e * EMB + nt * 8 + 2 * tig) = make_float2(h00, h01);
        }

        b ^= 1;
    }
}

extern "C" void kernel_launch(void* const* d_in, const int* in_sizes, int n_in,
                              void* d_out, int out_size)
{
    const float* rbf  = (const float*)d_in[0];
    const float* sph  = (const float*)d_in[1];
    const float* m    = (const float*)d_in[2];
    const float* w    = (const float*)d_in[3];
    const int*   idr  = (const int*)d_in[4];
    const int*   kidx = (const int*)d_in[5];

    const int nEdges = in_sizes[0] / (EMB * NSPH);
    const int nT     = in_sizes[4];

    int prep_elems = nT > 1024 ? nT : 1024;
    prep_kernel<<<(prep_elems + 255) / 256, 256>>>(idr, kidx, w, nT);

    static bool attr_set = false;
    if (!attr_set) {
        cudaFuncSetAttribute(main_kernel,
                             cudaFuncAttributeMaxDynamicSharedMemorySize,
                             SMEM_FLOATS * 4);
        attr_set = true;
    }
    main_kernel<<<NBLOCKS, 128, SMEM_FLOATS * 4>>>(rbf, sph, m, (float*)d_out, nEdges);
}

// round 16
// speedup vs baseline: 1.5605x; 1.5605x over previous
#include <cuda_runtime.h>

#define EMB   64
#define NSPH  16
#define KMAX  24
#define MAX_EDGES 131072

__device__ int    g_start[MAX_EDGES];
__device__ int    g_count[MAX_EDGES];
// W in mma-fragment order, 2 kt-frags packed per float4:
// g_Wf4[(j*8+nt)*32 + lane] = {b0(kt=2j), b1(kt=2j), b0(kt=2j+1), b1(kt=2j+1)}
__device__ float4 g_Wf4[32 * 32];

__global__ void prep_kernel(const int* __restrict__ id_reduce,
                            const int* __restrict__ Kidx,
                            const float* __restrict__ w, int nT)
{
    int t = blockIdx.x * blockDim.x + threadIdx.x;
    if (t < 1024) {
        int entry = t >> 5, lane = t & 31;
        int j  = entry >> 3, nt = entry & 7;
        int gid = lane >> 2, tig = lane & 3;
        int d = nt * 8 + gid;
        float v[4];
        #pragma unroll
        for (int h = 0; h < 2; h++) {
            int i = (2 * j + h) * 8 + tig;
            unsigned r0, r1;
            asm("cvt.rna.tf32.f32 %0, %1;" : "=r"(r0) : "f"(w[d * EMB + i]));
            asm("cvt.rna.tf32.f32 %0, %1;" : "=r"(r1) : "f"(w[d * EMB + i + 4]));
            v[2 * h]     = __uint_as_float(r0);
            v[2 * h + 1] = __uint_as_float(r1);
        }
        g_Wf4[t] = make_float4(v[0], v[1], v[2], v[3]);
    }
    if (t < nT) {
        int e = id_reduce[t];
        if (t == 0 || id_reduce[t - 1] != e) g_start[e] = t;
        if (t == nT - 1 || id_reduce[t + 1] != e) g_count[e] = Kidx[t] + 1;
    }
}

__device__ __forceinline__ unsigned tf32r(float x) {
    unsigned u; asm("cvt.rna.tf32.f32 %0, %1;" : "=r"(u) : "f"(x)); return u;
}

__device__ __forceinline__ void mma_tf32(float c[4], const unsigned a[4],
                                         unsigned b0, unsigned b1)
{
    asm volatile(
        "mma.sync.aligned.m16n8k8.row.col.f32.tf32.tf32.f32 "
        "{%0,%1,%2,%3},{%4,%5,%6,%7},{%8,%9},{%0,%1,%2,%3};"
        : "+f"(c[0]), "+f"(c[1]), "+f"(c[2]), "+f"(c[3])
        : "r"(a[0]), "r"(a[1]), "r"(a[2]), "r"(a[3]), "r"(b0), "r"(b1));
}

// One warp per edge (3 warps/block, 6 CTAs/SM -> 18 warps/SM). Streams staged
// via cp.async.cg into XOR-swizzled, pad-free, conflict-free smem:
//   rbf_s: rbf[i][s]  at i*16 + (s ^ ((i&2)<<2))   [s-xor-8 when i&2]
//   m_s:   m[t][d]    at t*64 + (d ^ ((t&3)*8)), rows >= count zfilled
//   s_s:   sph[s][k]  at s*24 + (k ^ (s&4))
// Pipeline: cp.async rbf (group0) -> cp.async m+sph (group1) -> wait 1 ->
// LDS ra -> P half (nt 0..3) -> wait 0 -> sa -> Q half + store -> P half
// (nt 4..7) -> Q half + store. nt-split halves p[] register pressure.
__global__ void __launch_bounds__(96, 6)
main_kernel(const float* __restrict__ rbf,
            const float* __restrict__ sph,
            const float* __restrict__ m,
            float* __restrict__ out, int nEdges)
{
    __shared__ __align__(16) float rbf_s[3][EMB * NSPH];   // 4KB/warp
    __shared__ __align__(16) float m_s[3][KMAX * EMB];     // 6KB/warp
    __shared__ __align__(16) float s_s[3][NSPH * KMAX];    // 1.5KB/warp

    const int lane = threadIdx.x & 31;
    const int wrp  = threadIdx.x >> 5;
    const int gid  = lane >> 2;   // 0..7
    const int tig  = lane & 3;    // 0..3

    const int e = blockIdx.x * 3 + wrp;
    if (e >= nEdges) return;

    const int st0 = __ldg(&g_start[e]);
    const int ct0 = __ldg(&g_count[e]);

    const unsigned rsb = (unsigned)__cvta_generic_to_shared(&rbf_s[wrp][0]);
    const unsigned msb = (unsigned)__cvta_generic_to_shared(&m_s[wrp][0]);
    const unsigned ssb = (unsigned)__cvta_generic_to_shared(&s_s[wrp][0]);

    // ---- group 0: rbf (4KB); swizzle: chunk ^ (row&2) == s-xor-8 when i&2 ----
    {
        const float* rg = rbf + (size_t)e * (EMB * NSPH);
        #pragma unroll
        for (int it = 0; it < 8; it++) {
            int chunk = it * 32 + lane;
            int row = chunk >> 2, c = chunk & 3;
            int dc = c ^ (row & 2);
            unsigned dst = rsb + (unsigned)(row * NSPH + dc * 4) * 4u;
            asm volatile("cp.async.cg.shared.global [%0], [%1], 16;"
                         :: "r"(dst), "l"(rg + chunk * 4));
        }
        asm volatile("cp.async.commit_group;");
    }

    // ---- group 1: m (zfilled) + sph ----
    {
        const float* mg = m + (size_t)st0 * EMB;
        #pragma unroll
        for (int it = 0; it < 12; it++) {
            int chunk = it * 32 + lane;
            int row = chunk >> 4, c = chunk & 15;
            int dc = c ^ ((row & 3) << 1);               // float-xor-(t&3)*8
            unsigned dst = msb + (unsigned)(row * EMB + dc * 4) * 4u;
            int srow = (row < ct0) ? row : 0;
            int sz   = (row < ct0) ? 16 : 0;
            asm volatile("cp.async.cg.shared.global [%0], [%1], 16, %2;"
                         :: "r"(dst), "l"(mg + srow * EMB + c * 4), "r"(sz));
        }
        const float* sg = sph + (size_t)e * (NSPH * KMAX);
        #pragma unroll
        for (int it = 0; it < 3; it++) {
            int chunk = it * 32 + lane;
            int row = chunk / 6, c = chunk % 6;
            int dc = c ^ ((row & 4) >> 2);               // float-xor-4 when s&4
            unsigned dst = ssb + (unsigned)(row * KMAX + dc * 4) * 4u;
            asm volatile("cp.async.cg.shared.global [%0], [%1], 16;"
                         :: "r"(dst), "l"(sg + row * KMAX + c * 4));
        }
        asm volatile("cp.async.commit_group;");
    }

    // ---- wait rbf; extract ra (conflict-free scalar LDS) ----
    asm volatile("cp.async.wait_group 1;");
    __syncwarp();

    unsigned ra[8][4];
    {
        const float* rp = &rbf_s[wrp][0];
        const int f = (tig & 2) << 2;                    // s-xor-8 when i&2
        #pragma unroll
        for (int kt = 0; kt < 8; kt++) {
            int i = kt * 8 + tig;
            ra[kt][0] = tf32r(rp[i * NSPH + (gid ^ f)]);
            ra[kt][1] = tf32r(rp[i * NSPH + ((gid + 8) ^ f)]);
            ra[kt][2] = tf32r(rp[(i + 4) * NSPH + (gid ^ f)]);
            ra[kt][3] = tf32r(rp[(i + 4) * NSPH + ((gid + 8) ^ f)]);
        }
    }

    // ---- P half 0 (nt 0..3) ----
    float p[4][4];
    #pragma unroll
    for (int nt = 0; nt < 4; nt++) {
        p[nt][0] = p[nt][1] = p[nt][2] = p[nt][3] = 0.f;
        #pragma unroll
        for (int j = 0; j < 4; j++) {
            float4 wf = __ldg(&g_Wf4[(j * 8 + nt) * 32 + lane]);
            mma_tf32(p[nt], ra[2 * j],     __float_as_uint(wf.x), __float_as_uint(wf.y));
            mma_tf32(p[nt], ra[2 * j + 1], __float_as_uint(wf.z), __float_as_uint(wf.w));
        }
    }

    // ---- wait m+sph; extract sa ----
    asm volatile("cp.async.wait_group 0;");
    __syncwarp();

    unsigned sa[3][4];
    {
        const float* sp = &s_s[wrp][0];
        const int h = gid & 4;
        #pragma unroll
        for (int kt = 0; kt < 3; kt++) {
            int t = kt * 8 + tig;
            sa[kt][0] = tf32r(sp[gid * KMAX + (t ^ h)]);
            sa[kt][1] = tf32r(sp[(gid + 8) * KMAX + (t ^ h)]);
            sa[kt][2] = tf32r(sp[gid * KMAX + ((t + 4) ^ h)]);
            sa[kt][3] = tf32r(sp[(gid + 8) * KMAX + ((t + 4) ^ h)]);
        }
    }

    const float* mp = &m_s[wrp][0];
    const int gsw = tig * 8;                              // m swizzle: d ^ ((t&3)*8)

    // ---- Q half 0 + Hadamard + reduce + store (nt 0..3) ----
    #pragma unroll
    for (int nt = 0; nt < 4; nt++) {
        float q[4] = {0.f, 0.f, 0.f, 0.f};
        #pragma unroll
        for (int kt = 0; kt < 3; kt++) {
            int t = kt * 8 + tig;
            int col = (nt * 8 + gid) ^ gsw;
            unsigned b0 = tf32r(mp[t * EMB + col]);
            unsigned b1 = tf32r(mp[(t + 4) * EMB + col]);
            mma_tf32(q, sa[kt], b0, b1);
        }
        float h00 = p[nt][0] * q[0] + p[nt][2] * q[2];
        float h01 = p[nt][1] * q[1] + p[nt][3] * q[3];
        #pragma unroll
        for (int off = 4; off <= 16; off <<= 1) {
            h00 += __shfl_xor_sync(0xffffffffu, h00, off);
            h01 += __shfl_xor_sync(0xffffffffu, h01, off);
        }
        if (gid == 0)
            *(float2*)(out + (size_t)e * EMB + nt * 8 + 2 * tig) = make_float2(h00, h01);
    }

    // ---- P half 1 (nt 4..7) ----
    #pragma unroll
    for (int nt = 0; nt < 4; nt++) {
        p[nt][0] = p[nt][1] = p[nt][2] = p[nt][3] = 0.f;
        #pragma unroll
        for (int j = 0; j < 4; j++) {
            float4 wf = __ldg(&g_Wf4[(j * 8 + nt + 4) * 32 + lane]);
            mma_tf32(p[nt], ra[2 * j],     __float_as_uint(wf.x), __float_as_uint(wf.y));
            mma_tf32(p[nt], ra[2 * j + 1], __float_as_uint(wf.z), __float_as_uint(wf.w));
        }
    }

    // ---- Q half 1 + Hadamard + reduce + store (nt 4..7) ----
    #pragma unroll
    for (int nt = 0; nt < 4; nt++) {
        int ntg = nt + 4;
        float q[4] = {0.f, 0.f, 0.f, 0.f};
        #pragma unroll
        for (int kt = 0; kt < 3; kt++) {
            int t = kt * 8 + tig;
            int col = (ntg * 8 + gid) ^ gsw;
            unsigned b0 = tf32r(mp[t * EMB + col]);
            unsigned b1 = tf32r(mp[(t + 4) * EMB + col]);
            mma_tf32(q, sa[kt], b0, b1);
        }
        float h00 = p[nt][0] * q[0] + p[nt][2] * q[2];
        float h01 = p[nt][1] * q[1] + p[nt][3] * q[3];
        #pragma unroll
        for (int off = 4; off <= 16; off <<= 1) {
            h00 += __shfl_xor_sync(0xffffffffu, h00, off);
            h01 += __shfl_xor_sync(0xffffffffu, h01, off);
        }
        if (gid == 0)
            *(float2*)(out + (size_t)e * EMB + ntg * 8 + 2 * tig) = make_float2(h00, h01);
    }
}

extern "C" void kernel_launch(void* const* d_in, const int* in_sizes, int n_in,
                              void* d_out, int out_size)
{
    const float* rbf  = (const float*)d_in[0];
    const float* sph  = (const float*)d_in[1];
    const float* m    = (const float*)d_in[2];
    const float* w    = (const float*)d_in[3];
    const int*   idr  = (const int*)d_in[4];
    const int*   kidx = (const int*)d_in[5];

    const int nEdges = in_sizes[0] / (EMB * NSPH);
    const int nT     = in_sizes[4];

    int prep_elems = nT > 1024 ? nT : 1024;
    prep_kernel<<<(prep_elems + 255) / 256, 256>>>(idr, kidx, w, nT);

    main_kernel<<<(nEdges + 2) / 3, 96>>>(rbf, sph, m, (float*)d_out, nEdges);
}

// round 17
// speedup vs baseline: 1.6163x; 1.0358x over previous
#include <cuda_runtime.h>

#define EMB   64
#define NSPH  16
#define KMAX  24
#define MAX_EDGES 131072
#define EPW   8      // edges per warp, software-pipelined

__device__ int    g_start[MAX_EDGES];
__device__ int    g_count[MAX_EDGES];
// W in mma-fragment order, 2 kt-frags packed per float4:
// g_Wf4[(j*8+nt)*32 + lane] = {b0(kt=2j), b1(kt=2j), b0(kt=2j+1), b1(kt=2j+1)}
__device__ float4 g_Wf4[32 * 32];

__global__ void prep_kernel(const int* __restrict__ id_reduce,
                            const int* __restrict__ Kidx,
                            const float* __restrict__ w, int nT)
{
    int t = blockIdx.x * blockDim.x + threadIdx.x;
    if (t < 1024) {
        int entry = t >> 5, lane = t & 31;
        int j  = entry >> 3, nt = entry & 7;
        int gid = lane >> 2, tig = lane & 3;
        int d = nt * 8 + gid;
        float v[4];
        #pragma unroll
        for (int h = 0; h < 2; h++) {
            int i = (2 * j + h) * 8 + tig;
            unsigned r0, r1;
            asm("cvt.rna.tf32.f32 %0, %1;" : "=r"(r0) : "f"(w[d * EMB + i]));
            asm("cvt.rna.tf32.f32 %0, %1;" : "=r"(r1) : "f"(w[d * EMB + i + 4]));
            v[2 * h]     = __uint_as_float(r0);
            v[2 * h + 1] = __uint_as_float(r1);
        }
        g_Wf4[t] = make_float4(v[0], v[1], v[2], v[3]);
    }
    if (t < nT) {
        int e = id_reduce[t];
        if (t == 0 || id_reduce[t - 1] != e) g_start[e] = t;
        if (t == nT - 1 || id_reduce[t + 1] != e) g_count[e] = Kidx[t] + 1;
    }
}

__device__ __forceinline__ unsigned tf32r(float x) {
    unsigned u; asm("cvt.rna.tf32.f32 %0, %1;" : "=r"(u) : "f"(x)); return u;
}

__device__ __forceinline__ void mma_tf32(float c[4], const unsigned a[4],
                                         unsigned b0, unsigned b1)
{
    asm volatile(
        "mma.sync.aligned.m16n8k8.row.col.f32.tf32.tf32.f32 "
        "{%0,%1,%2,%3},{%4,%5,%6,%7},{%8,%9},{%0,%1,%2,%3};"
        : "+f"(c[0]), "+f"(c[1]), "+f"(c[2]), "+f"(c[3])
        : "r"(a[0]), "r"(a[1]), "r"(a[2]), "r"(a[3]), "r"(b0), "r"(b1));
}

// group A: rbf[i][s] at i*16 + (s ^ ((i&2)<<2))  [chunk ^ (row&2)]
__device__ __forceinline__ void issue_rbf(const float* __restrict__ rbf, int e,
                                          unsigned rsb, int lane)
{
    const float* rg = rbf + (size_t)e * (EMB * NSPH);
    #pragma unroll
    for (int it = 0; it < 8; it++) {
        int chunk = it * 32 + lane;
        int row = chunk >> 2, c = chunk & 3;
        int dc = c ^ (row & 2);
        unsigned dst = rsb + (unsigned)(row * NSPH + dc * 4) * 4u;
        asm volatile("cp.async.cg.shared.global [%0], [%1], 16;"
                     :: "r"(dst), "l"(rg + chunk * 4));
    }
    asm volatile("cp.async.commit_group;");
}

// group B: m[t][d] at t*64 + (d ^ ((t&3)*8)), rows >= ct zfilled; sph[s][k] at s*24 + (k ^ (s&4))
__device__ __forceinline__ void issue_msph(const float* __restrict__ sph,
                                           const float* __restrict__ m,
                                           int e, int st, int ct,
                                           unsigned msb, unsigned ssb, int lane)
{
    const float* mg = m + (size_t)st * EMB;
    #pragma unroll
    for (int it = 0; it < 12; it++) {
        int chunk = it * 32 + lane;
        int row = chunk >> 4, c = chunk & 15;
        int dc = c ^ ((row & 3) << 1);
        unsigned dst = msb + (unsigned)(row * EMB + dc * 4) * 4u;
        int srow = (row < ct) ? row : 0;
        int sz   = (row < ct) ? 16 : 0;
        asm volatile("cp.async.cg.shared.global [%0], [%1], 16, %2;"
                     :: "r"(dst), "l"(mg + srow * EMB + c * 4), "r"(sz));
    }
    const float* sg = sph + (size_t)e * (NSPH * KMAX);
    #pragma unroll
    for (int it = 0; it < 3; it++) {
        int chunk = it * 32 + lane;
        int row = chunk / 6, c = chunk % 6;
        int dc = c ^ ((row & 4) >> 2);
        unsigned dst = ssb + (unsigned)(row * KMAX + dc * 4) * 4u;
        asm volatile("cp.async.cg.shared.global [%0], [%1], 16;"
                     :: "r"(dst), "l"(sg + row * KMAX + c * 4));
    }
    asm volatile("cp.async.commit_group;");
}

// One warp handles EPW consecutive edges, distance-1 pipelined over single
// buffers (safe: next group issued only after this edge's LDS reads retire;
// cp.async data arrives >=600cyc later). Per-iteration commit order A(rbf),
// B(m+sph); entry wait_group 1 drains A_i, mid wait_group 1 drains B_i.
__global__ void __launch_bounds__(128, 4)
main_kernel(const float* __restrict__ rbf,
            const float* __restrict__ sph,
            const float* __restrict__ m,
            float* __restrict__ out, int nEdges)
{
    __shared__ __align__(16) float rbf_s[4][EMB * NSPH];   // 4KB/warp
    __shared__ __align__(16) float m_s[4][KMAX * EMB];     // 6KB/warp
    __shared__ __align__(16) float s_s[4][NSPH * KMAX];    // 1.5KB/warp

    const int lane = threadIdx.x & 31;
    const int wrp  = threadIdx.x >> 5;
    const int gid  = lane >> 2;   // 0..7
    const int tig  = lane & 3;    // 0..3

    const float* rp = &rbf_s[wrp][0];
    const float* sp = &s_s[wrp][0];
    const float* mp = &m_s[wrp][0];
    const unsigned rsb = (unsigned)__cvta_generic_to_shared(rp);
    const unsigned msb = (unsigned)__cvta_generic_to_shared(mp);
    const unsigned ssb = (unsigned)__cvta_generic_to_shared(sp);

    const int e0 = (blockIdx.x * 4 + wrp) * EPW;
    if (e0 >= nEdges) return;

    // ---- prologue: stage edge e0; prefetch e0+1 run info ----
    {
        int st = __ldg(&g_start[e0]);
        int ct = __ldg(&g_count[e0]);
        issue_rbf(rbf, e0, rsb, lane);
        issue_msph(sph, m, e0, st, ct, msb, ssb, lane);
    }
    int en = (e0 + 1 < nEdges) ? e0 + 1 : e0;
    int stN = __ldg(&g_start[en]);
    int ctN = __ldg(&g_count[en]);

    #pragma unroll 1
    for (int i = 0; i < EPW; i++) {
        const int e = e0 + i;
        if (e >= nEdges) break;
        const bool more = (i + 1 < EPW) && (e + 1 < nEdges);

        // ---- wait A_i (rbf); B_i may pend ----
        asm volatile("cp.async.wait_group 1;");
        __syncwarp();

        unsigned ra[8][4];
        {
            const int f = (tig & 2) << 2;             // s-xor-8 when i&2
            #pragma unroll
            for (int kt = 0; kt < 8; kt++) {
                int ii = kt * 8 + tig;
                ra[kt][0] = tf32r(rp[ii * NSPH + (gid ^ f)]);
                ra[kt][1] = tf32r(rp[ii * NSPH + ((gid + 8) ^ f)]);
                ra[kt][2] = tf32r(rp[(ii + 4) * NSPH + (gid ^ f)]);
                ra[kt][3] = tf32r(rp[(ii + 4) * NSPH + ((gid + 8) ^ f)]);
            }
        }

        // ---- issue A_{i+1} into the (now-consumed) rbf buffer ----
        if (more) issue_rbf(rbf, e + 1, rsb, lane);

        // ---- P phase ----
        float p[8][4];
        #pragma unroll
        for (int nt = 0; nt < 8; nt++) {
            p[nt][0] = p[nt][1] = p[nt][2] = p[nt][3] = 0.f;
            #pragma unroll
            for (int j = 0; j < 4; j++) {
                float4 wf = __ldg(&g_Wf4[(j * 8 + nt) * 32 + lane]);
                mma_tf32(p[nt], ra[2 * j],     __float_as_uint(wf.x), __float_as_uint(wf.y));
                mma_tf32(p[nt], ra[2 * j + 1], __float_as_uint(wf.z), __float_as_uint(wf.w));
            }
        }

        // ---- wait B_i (m+sph); A_{i+1} may pend ----
        if (more) { asm volatile("cp.async.wait_group 1;"); }
        else      { asm volatile("cp.async.wait_group 0;"); }
        __syncwarp();

        unsigned sa[3][4];
        {
            const int h = gid & 4;
            #pragma unroll
            for (int kt = 0; kt < 3; kt++) {
                int t = kt * 8 + tig;
                sa[kt][0] = tf32r(sp[gid * KMAX + (t ^ h)]);
                sa[kt][1] = tf32r(sp[(gid + 8) * KMAX + (t ^ h)]);
                sa[kt][2] = tf32r(sp[gid * KMAX + ((t + 4) ^ h)]);
                sa[kt][3] = tf32r(sp[(gid + 8) * KMAX + ((t + 4) ^ h)]);
            }
        }

        // ---- Q phase + Hadamard + reduce + store ----
        const int gsw = tig * 8;                      // m swizzle: d ^ ((t&3)*8)
        #pragma unroll
        for (int nt = 0; nt < 8; nt++) {
            float q[4] = {0.f, 0.f, 0.f, 0.f};
            #pragma unroll
            for (int kt = 0; kt < 3; kt++) {
                int t = kt * 8 + tig;
                int col = (nt * 8 + gid) ^ gsw;
                unsigned b0 = tf32r(mp[t * EMB + col]);
                unsigned b1 = tf32r(mp[(t + 4) * EMB + col]);
                mma_tf32(q, sa[kt], b0, b1);
            }
            float h00 = p[nt][0] * q[0] + p[nt][2] * q[2];
            float h01 = p[nt][1] * q[1] + p[nt][3] * q[3];
            #pragma unroll
            for (int off = 4; off <= 16; off <<= 1) {
                h00 += __shfl_xor_sync(0xffffffffu, h00, off);
                h01 += __shfl_xor_sync(0xffffffffu, h01, off);
            }
            if (gid == 0)
                *(float2*)(out + (size_t)e * EMB + nt * 8 + 2 * tig) = make_float2(h00, h01);
        }

        // ---- issue B_{i+1} (m buffer free after Q); prefetch run info e+2 ----
        if (more) {
            issue_msph(sph, m, e + 1, stN, ctN, msb, ssb, lane);
            int e2 = (e + 2 < nEdges) ? e + 2 : e + 1;
            stN = __ldg(&g_start[e2]);
            ctN = __ldg(&g_count[e2]);
        }
    }
}

extern "C" void kernel_launch(void* const* d_in, const int* in_sizes, int n_in,
                              void* d_out, int out_size)
{
    const float* rbf  = (const float*)d_in[0];
    const float* sph  = (const float*)d_in[1];
    const float* m    = (const float*)d_in[2];
    const float* w    = (const float*)d_in[3];
    const int*   idr  = (const int*)d_in[4];
    const int*   kidx = (const int*)d_in[5];

    const int nEdges = in_sizes[0] / (EMB * NSPH);
    const int nT     = in_sizes[4];

    int prep_elems = nT > 1024 ? nT : 1024;
    prep_kernel<<<(prep_elems + 255) / 256, 256>>>(idr, kidx, w, nT);

    const int nwarps  = (nEdges + EPW - 1) / EPW;
    const int nblocks = (nwarps + 3) / 4;
    main_kernel<<<nblocks, 128>>>(rbf, sph, m, (float*)d_out, nEdges);
}